// round 1
// baseline (speedup 1.0000x reference)
#include <cuda_runtime.h>

#define DIM 256
#define OUT 8

// ---- packed f32x2 helpers (B300 dual-rate fp32 FMA; only reachable via PTX) ----
__device__ __forceinline__ unsigned long long pk2(float lo, float hi) {
    unsigned long long r;
    asm("mov.b64 %0, {%1,%2};" : "=l"(r) : "f"(lo), "f"(hi));
    return r;
}
__device__ __forceinline__ void upk2(unsigned long long v, float& lo, float& hi) {
    asm("mov.b64 {%0,%1}, %2;" : "=f"(lo), "=f"(hi) : "l"(v));
}
__device__ __forceinline__ unsigned long long fma2(unsigned long long a, unsigned long long b,
                                                   unsigned long long c) {
    unsigned long long d;
    asm("fma.rn.f32x2 %0, %1, %2, %3;" : "=l"(d) : "l"(a), "l"(b), "l"(c));
    return d;
}
__device__ __forceinline__ unsigned long long mul2(unsigned long long a, unsigned long long b) {
    unsigned long long d;
    asm("mul.rn.f32x2 %0, %1, %2;" : "=l"(d) : "l"(a), "l"(b));
    return d;
}

__global__ __launch_bounds__(256, 2)
void ffn_kernel(const float* __restrict__ x, const float* __restrict__ W1,
                const float* __restrict__ b1, const float* __restrict__ W2,
                const float* __restrict__ b2, const float* __restrict__ gamma,
                const float* __restrict__ beta, float* __restrict__ out, int ntok)
{
    __shared__ float sW2[64], sb1[8], sb2[8], sg[8], sbeta[8];
    int tid = threadIdx.x;
    if (tid < 64) sW2[tid] = W2[tid];
    if (tid < 8) { sb1[tid] = b1[tid]; sb2[tid] = b2[tid]; sg[tid] = gamma[tid]; sbeta[tid] = beta[tid]; }
    __syncthreads();

    const int lane = tid & 31;
    const int warp_global = blockIdx.x * (blockDim.x >> 5) + (tid >> 5);
    const int nwarps = gridDim.x * (blockDim.x >> 5);

    // ---- W1 slice into registers, packed over output-channel pairs ----
    // lane covers elements [4*lane .. 4*lane+3] and [128+4*lane .. 128+4*lane+3]
    // Wp[k][o2] = { W1[2*o2][elem_k], W1[2*o2+1][elem_k] }
    unsigned long long Wp[8][4];
    #pragma unroll
    for (int o2 = 0; o2 < 4; o2++) {
        float4 r0a = *(const float4*)(W1 + (2 * o2) * DIM + 4 * lane);
        float4 r1a = *(const float4*)(W1 + (2 * o2 + 1) * DIM + 4 * lane);
        float4 r0b = *(const float4*)(W1 + (2 * o2) * DIM + 128 + 4 * lane);
        float4 r1b = *(const float4*)(W1 + (2 * o2 + 1) * DIM + 128 + 4 * lane);
        Wp[0][o2] = pk2(r0a.x, r1a.x);
        Wp[1][o2] = pk2(r0a.y, r1a.y);
        Wp[2][o2] = pk2(r0a.z, r1a.z);
        Wp[3][o2] = pk2(r0a.w, r1a.w);
        Wp[4][o2] = pk2(r0b.x, r1b.x);
        Wp[5][o2] = pk2(r0b.y, r1b.y);
        Wp[6][o2] = pk2(r0b.z, r1b.z);
        Wp[7][o2] = pk2(r0b.w, r1b.w);
    }

    const float4* x4 = (const float4*)x;
    const int ngroups = (ntok + 31) >> 5;

    for (int g = warp_global; g < ngroups; g += nwarps) {
        const int base = g << 5;
        const int nt = min(32, ntok - base);
        float myh[8];

        #pragma unroll 2
        for (int t = 0; t < nt; t++) {
            const float4* row = x4 + (size_t)(base + t) * (DIM / 4);
            float4 a = row[lane];
            float4 b = row[32 + lane];
            float av[8] = {a.x, a.y, a.z, a.w, b.x, b.y, b.z, b.w};

            // GEMM1 partials: 8 outputs as 4 packed pairs
            unsigned long long acc[4];
            {
                unsigned long long xx = pk2(av[0], av[0]);
                #pragma unroll
                for (int o2 = 0; o2 < 4; o2++) acc[o2] = mul2(xx, Wp[0][o2]);
                #pragma unroll
                for (int k = 1; k < 8; k++) {
                    xx = pk2(av[k], av[k]);
                    #pragma unroll
                    for (int o2 = 0; o2 < 4; o2++) acc[o2] = fma2(xx, Wp[k][o2], acc[o2]);
                }
            }
            float v[8];
            #pragma unroll
            for (int o2 = 0; o2 < 4; o2++) upk2(acc[o2], v[2 * o2], v[2 * o2 + 1]);

            // ---- segmented butterfly reduce: split value set at xor16/8/4 ----
            // after xor4, lane holds full-partial of value index (lane>>2)
            {
                bool up = (lane & 16) != 0;
                #pragma unroll
                for (int i = 0; i < 4; i++) {
                    float send = up ? v[i] : v[i + 4];
                    float recv = __shfl_xor_sync(0xffffffffu, send, 16);
                    v[i] = (up ? v[i + 4] : v[i]) + recv;
                }
            }
            {
                bool up = (lane & 8) != 0;
                #pragma unroll
                for (int i = 0; i < 2; i++) {
                    float send = up ? v[i] : v[i + 2];
                    float recv = __shfl_xor_sync(0xffffffffu, send, 8);
                    v[i] = (up ? v[i + 2] : v[i]) + recv;
                }
            }
            {
                bool up = (lane & 4) != 0;
                float send = up ? v[0] : v[1];
                float recv = __shfl_xor_sync(0xffffffffu, send, 4);
                v[0] = (up ? v[1] : v[0]) + recv;
            }
            v[0] += __shfl_xor_sync(0xffffffffu, v[0], 2);
            v[0] += __shfl_xor_sync(0xffffffffu, v[0], 1);
            // lane now holds h[lane>>2] for token base+t

            // gather the 8 outputs; park on the token's owner lane
            #pragma unroll
            for (int o = 0; o < 8; o++) {
                float hv = __shfl_sync(0xffffffffu, v[0], o << 2);
                if (lane == t) myh[o] = hv;
            }
        }

        // ---- lane-distributed epilogue: lane L owns token base+L ----
        if (lane < nt) {
            const int tok = base + lane;
            float gg[8];
            #pragma unroll
            for (int o = 0; o < 8; o++) {
                float hv = myh[o] + sb1[o];
                gg[o] = 0.5f * hv * (1.0f + erff(hv * 0.70710678118654752440f));
            }
            float y[8];
            #pragma unroll
            for (int p = 0; p < 8; p++) {
                float s = sb2[p];
                #pragma unroll
                for (int o = 0; o < 8; o++) s = fmaf(sW2[p * 8 + o], gg[o], s);
                y[p] = s;
            }
            float mu = 0.0f;
            #pragma unroll
            for (int p = 0; p < 8; p++) mu += y[p];
            mu *= 0.125f;
            float var = 0.0f;
            #pragma unroll
            for (int p = 0; p < 8; p++) {
                float d = y[p] - mu;
                var = fmaf(d, d, var);
            }
            var *= 0.125f;
            float rs = rsqrtf(var + 1e-5f);

            float4 o0, o1;
            o0.x = (y[0] - mu) * rs * sg[0] + sbeta[0];
            o0.y = (y[1] - mu) * rs * sg[1] + sbeta[1];
            o0.z = (y[2] - mu) * rs * sg[2] + sbeta[2];
            o0.w = (y[3] - mu) * rs * sg[3] + sbeta[3];
            o1.x = (y[4] - mu) * rs * sg[4] + sbeta[4];
            o1.y = (y[5] - mu) * rs * sg[5] + sbeta[5];
            o1.z = (y[6] - mu) * rs * sg[6] + sbeta[6];
            o1.w = (y[7] - mu) * rs * sg[7] + sbeta[7];
            float4* op = (float4*)(out + (size_t)tok * 8);
            op[0] = o0;
            op[1] = o1;
        }
    }
}

extern "C" void kernel_launch(void* const* d_in, const int* in_sizes, int n_in,
                              void* d_out, int out_size)
{
    const float* x     = (const float*)d_in[0];
    const float* W1    = (const float*)d_in[1];
    const float* b1    = (const float*)d_in[2];
    const float* W2    = (const float*)d_in[3];
    const float* b2    = (const float*)d_in[4];
    const float* gamma = (const float*)d_in[5];
    const float* beta  = (const float*)d_in[6];
    float* out = (float*)d_out;

    int ntok = in_sizes[0] / DIM;           // 262144 for the bench shape
    int ngroups = (ntok + 31) >> 5;
    int blocks = (ngroups + 7) >> 3;        // 8 warps per block, 1 group per warp
    if (blocks > 1024) blocks = 1024;
    if (blocks < 1) blocks = 1;

    ffn_kernel<<<blocks, 256>>>(x, W1, b1, W2, b2, gamma, beta, out, ntok);
}

// round 3
// speedup vs baseline: 1.7583x; 1.7583x over previous
#include <cuda_runtime.h>
#include <cstdint>

#define DIM 256
#define OUT 8
#define CHUNK 32          // dims per pipeline chunk
#define NCHUNK 8          // DIM / CHUNK
#define ROWF 36           // floats per row in smem tile (CHUNK + 4 pad -> conflict-free LDS.128)
#define TPW 32            // tokens per warp group (1 per lane)
#define WARPS 8           // warps per block

// smem layout (dynamic):
//   [0, XBUF_BYTES)            per-warp double-buffered x tiles: [WARPS][2][TPW*ROWF] floats
//   [XBUF_BYTES, +8192)        Wp: packed W1 dim-pairs, Wp[d*8+o] = {W1[o][2d], W1[o][2d+1]}
//   then sW2[64], sb1[8], sb2[8], sg[8], sbeta[8]
#define XBUF_FLOATS (WARPS * 2 * TPW * ROWF)
#define XBUF_BYTES  (XBUF_FLOATS * 4)
#define WP_BYTES    (DIM / 2 * OUT * 8)
#define SMEM_TOTAL  (XBUF_BYTES + WP_BYTES + 96 * 4)

__device__ __forceinline__ unsigned long long pk2(float lo, float hi) {
    unsigned long long r;
    asm("mov.b64 %0, {%1,%2};" : "=l"(r) : "f"(lo), "f"(hi));
    return r;
}
__device__ __forceinline__ unsigned long long fma2(unsigned long long a, unsigned long long b,
                                                   unsigned long long c) {
    unsigned long long d;
    asm("fma.rn.f32x2 %0, %1, %2, %3;" : "=l"(d) : "l"(a), "l"(b), "l"(c));
    return d;
}
__device__ __forceinline__ void cp16(uint32_t saddr, const float* gptr) {
    asm volatile("cp.async.cg.shared.global [%0], [%1], 16;" :: "r"(saddr), "l"(gptr));
}

__global__ __launch_bounds__(256, 2)
void ffn_kernel(const float* __restrict__ x, const float* __restrict__ W1,
                const float* __restrict__ b1, const float* __restrict__ W2,
                const float* __restrict__ b2, const float* __restrict__ gamma,
                const float* __restrict__ beta, float* __restrict__ out, int ntok)
{
    extern __shared__ char smem_raw[];
    float* xbuf = (float*)smem_raw;
    unsigned long long* Wp = (unsigned long long*)(smem_raw + XBUF_BYTES);
    float* tail = (float*)(smem_raw + XBUF_BYTES + WP_BYTES);
    float* sW2 = tail;          // 64
    float* sb1 = tail + 64;     // 8
    float* sb2 = tail + 72;     // 8
    float* sg  = tail + 80;     // 8
    float* sbt = tail + 88;     // 8

    const int tid = threadIdx.x;

    // ---- one-time init: packed W1 + epilogue params ----
    {
        int e = tid * 4;            // 256 threads x 4 = 1024 entries = 128 dp x 8 out
        #pragma unroll
        for (int q = 0; q < 4; q++) {
            int idx = e + q;
            int d = idx >> 3;
            int o = idx & 7;
            Wp[idx] = pk2(W1[o * DIM + 2 * d], W1[o * DIM + 2 * d + 1]);
        }
        if (tid < 64) sW2[tid] = W2[tid];
        if (tid < 8) { sb1[tid] = b1[tid]; sb2[tid] = b2[tid]; sg[tid] = gamma[tid]; sbt[tid] = beta[tid]; }
    }
    __syncthreads();

    const int lane = tid & 31;
    const int warp = tid >> 5;
    const int warp_global = blockIdx.x * WARPS + warp;
    const int nwarps = gridDim.x * WARPS;
    const int ngroups = (ntok + TPW - 1) / TPW;

    float* wtile = xbuf + warp * 2 * (TPW * ROWF);          // this warp's double buffer
    const uint32_t wtile_su = (uint32_t)__cvta_generic_to_shared(wtile);

    // staging address components for this lane (it = 0..7, lin = it*32+lane)
    // r = lin>>3, j = lin&7 ; smem dst = stg*TPW*ROWF + r*ROWF + j*4 floats

    for (int g = warp_global; g < ngroups; g += nwarps) {
        const int base = g * TPW;

        // ---- prefetch chunk 0 into stage 0 ----
        {
            #pragma unroll
            for (int it = 0; it < 8; it++) {
                int lin = it * 32 + lane;
                int r = lin >> 3, j = lin & 7;
                int tok = base + r;
                if (tok < ntok)
                    cp16(wtile_su + (uint32_t)(r * ROWF + j * 4) * 4,
                         x + (size_t)tok * DIM + 0 * CHUNK + j * 4);
            }
            asm volatile("cp.async.commit_group;");
        }

        unsigned long long acc[OUT];
        #pragma unroll
        for (int o = 0; o < OUT; o++) acc[o] = 0ull;

        const float* myrow_base = wtile + lane * ROWF;

        #pragma unroll
        for (int c = 0; c < NCHUNK; c++) {
            // prefetch next chunk into the other stage
            if (c + 1 < NCHUNK) {
                const int stg = (c + 1) & 1;
                #pragma unroll
                for (int it = 0; it < 8; it++) {
                    int lin = it * 32 + lane;
                    int r = lin >> 3, j = lin & 7;
                    int tok = base + r;
                    if (tok < ntok)
                        cp16(wtile_su + (uint32_t)(stg * TPW * ROWF + r * ROWF + j * 4) * 4,
                             x + (size_t)tok * DIM + (c + 1) * CHUNK + j * 4);
                }
                asm volatile("cp.async.commit_group;");
                asm volatile("cp.async.wait_group 1;");
            } else {
                asm volatile("cp.async.wait_group 0;");
            }
            __syncwarp();

            // ---- compute chunk c from stage (c&1) ----
            const float* myrow = myrow_base + (c & 1) * (TPW * ROWF);
            #pragma unroll
            for (int i = 0; i < 8; i++) {
                ulonglong2 xv = *(const ulonglong2*)(myrow + i * 4);
                const int dpg = c * 16 + 2 * i;          // global dim-pair index
                const ulonglong2* w = (const ulonglong2*)(Wp + dpg * OUT);
                ulonglong2 w0 = w[0], w1 = w[1], w2 = w[2], w3 = w[3];
                acc[0] = fma2(xv.x, w0.x, acc[0]);
                acc[1] = fma2(xv.x, w0.y, acc[1]);
                acc[2] = fma2(xv.x, w1.x, acc[2]);
                acc[3] = fma2(xv.x, w1.y, acc[3]);
                acc[4] = fma2(xv.x, w2.x, acc[4]);
                acc[5] = fma2(xv.x, w2.y, acc[5]);
                acc[6] = fma2(xv.x, w3.x, acc[6]);
                acc[7] = fma2(xv.x, w3.y, acc[7]);
                ulonglong2 w4 = w[4], w5 = w[5], w6 = w[6], w7 = w[7];
                acc[0] = fma2(xv.y, w4.x, acc[0]);
                acc[1] = fma2(xv.y, w4.y, acc[1]);
                acc[2] = fma2(xv.y, w5.x, acc[2]);
                acc[3] = fma2(xv.y, w5.y, acc[3]);
                acc[4] = fma2(xv.y, w6.x, acc[4]);
                acc[5] = fma2(xv.y, w6.y, acc[5]);
                acc[6] = fma2(xv.y, w7.x, acc[6]);
                acc[7] = fma2(xv.y, w7.y, acc[7]);
            }
            __syncwarp();
        }

        // ---- per-thread epilogue: this thread owns token base+lane ----
        const int tok = base + lane;
        if (tok < ntok) {
            float gg[OUT];
            #pragma unroll
            for (int o = 0; o < OUT; o++) {
                float2 p = *(float2*)&acc[o];
                float hv = p.x + p.y + sb1[o];
                gg[o] = 0.5f * hv * (1.0f + erff(hv * 0.70710678118654752440f));
            }
            float y[OUT];
            #pragma unroll
            for (int p = 0; p < OUT; p++) {
                float s = sb2[p];
                #pragma unroll
                for (int o = 0; o < OUT; o++) s = fmaf(sW2[p * 8 + o], gg[o], s);
                y[p] = s;
            }
            float mu = 0.0f;
            #pragma unroll
            for (int p = 0; p < OUT; p++) mu += y[p];
            mu *= 0.125f;
            float var = 0.0f;
            #pragma unroll
            for (int p = 0; p < OUT; p++) {
                float d = y[p] - mu;
                var = fmaf(d, d, var);
            }
            var *= 0.125f;
            float rs = rsqrtf(var + 1e-5f);

            float4 o0, o1;
            o0.x = (y[0] - mu) * rs * sg[0] + sbt[0];
            o0.y = (y[1] - mu) * rs * sg[1] + sbt[1];
            o0.z = (y[2] - mu) * rs * sg[2] + sbt[2];
            o0.w = (y[3] - mu) * rs * sg[3] + sbt[3];
            o1.x = (y[4] - mu) * rs * sg[4] + sbt[4];
            o1.y = (y[5] - mu) * rs * sg[5] + sbt[5];
            o1.z = (y[6] - mu) * rs * sg[6] + sbt[6];
            o1.w = (y[7] - mu) * rs * sg[7] + sbt[7];
            float4* op = (float4*)(out + (size_t)tok * 8);
            op[0] = o0;
            op[1] = o1;
        }
        __syncwarp();   // protect tile reuse across group iterations
    }
}

extern "C" void kernel_launch(void* const* d_in, const int* in_sizes, int n_in,
                              void* d_out, int out_size)
{
    const float* x     = (const float*)d_in[0];
    const float* W1    = (const float*)d_in[1];
    const float* b1    = (const float*)d_in[2];
    const float* W2    = (const float*)d_in[3];
    const float* b2    = (const float*)d_in[4];
    const float* gamma = (const float*)d_in[5];
    const float* beta  = (const float*)d_in[6];
    float* out = (float*)d_out;

    int ntok = in_sizes[0] / DIM;               // 262144 for the bench shape
    int ngroups = (ntok + TPW - 1) / TPW;       // warp-groups of 32 tokens
    int blocks = (ngroups + WARPS - 1) / WARPS;
    if (blocks > 1024) blocks = 1024;
    if (blocks < 1) blocks = 1;

    cudaFuncSetAttribute(ffn_kernel, cudaFuncAttributeMaxDynamicSharedMemorySize, SMEM_TOTAL);
    ffn_kernel<<<blocks, 256, SMEM_TOTAL>>>(x, W1, b1, W2, b2, gamma, beta, out, ntok);
}